// round 11
// baseline (speedup 1.0000x reference)
#include <cuda_runtime.h>
#include <cuda_fp16.h>
#include <math.h>

#define BB   512
#define FREQ 8
#define EE   1024
#define HH   8
#define HD   128
#define DIN  3072
#define LROWS 4096
#define SEQ  512
#define NH   64
#define LDQKV (3 * EE * FREQ)   // 24576 halfs between consecutive l (fixed n)

// fp16 tensors
__device__ __half g_xh[LROWS * DIN];
__device__ __half g_zh[LROWS * EE];
__device__ __half g_qkvh[LROWS * 3 * EE];
__device__ __half g_ph[NH * SEQ * SEQ];    // scores then P (in-place softmax)
__device__ __half g_aoh[LROWS * EE];
__device__ __half g_zrech[LROWS * EE];
__device__ __half g_encWh[DIN * EE];       // enc_W [3072][1024] (NN operand)
__device__ __half g_inprojh[3 * EE * EE];  // [3072][1024] (NT operand)
__device__ __half g_outh[EE * EE];         // [1024][1024] (NT operand)
__device__ __half g_decWh[EE * DIN];       // dec_W [1024][3072] (NN operand)

// ---------------- helpers ----------------
__device__ __forceinline__ unsigned smem_u32(const void* p) {
    unsigned a;
    asm("{ .reg .u64 t; cvta.to.shared.u64 t, %1; cvt.u32.u64 %0, t; }"
        : "=r"(a) : "l"(p));
    return a;
}
__device__ __forceinline__ void cp16(unsigned dst, const void* src) {
    asm volatile("cp.async.cg.shared.global [%0], [%1], 16;" :: "r"(dst), "l"(src));
}
__device__ __forceinline__ void mma_f16(float c[4], const unsigned a[4], const unsigned b[2]) {
    asm volatile(
        "mma.sync.aligned.m16n8k16.row.col.f32.f16.f16.f32 "
        "{%0,%1,%2,%3}, {%4,%5,%6,%7}, {%8,%9}, {%0,%1,%2,%3};\n"
        : "+f"(c[0]), "+f"(c[1]), "+f"(c[2]), "+f"(c[3])
        : "r"(a[0]), "r"(a[1]), "r"(a[2]), "r"(a[3]), "r"(b[0]), "r"(b[1]));
}
__device__ __forceinline__ void ldm_x4(unsigned* r, unsigned addr) {
    asm volatile("ldmatrix.sync.aligned.m8n8.x4.shared.b16 {%0,%1,%2,%3}, [%4];"
        : "=r"(r[0]), "=r"(r[1]), "=r"(r[2]), "=r"(r[3]) : "r"(addr));
}
__device__ __forceinline__ void ldm_x4t(unsigned* r, unsigned addr) {
    asm volatile("ldmatrix.sync.aligned.m8n8.x4.trans.shared.b16 {%0,%1,%2,%3}, [%4];"
        : "=r"(r[0]), "=r"(r[1]), "=r"(r[2]), "=r"(r[3]) : "r"(addr));
}

// ---------------- fp16 GEMM ----------------
// C = alpha * A @ op(B) + bias.  A:[M,K] half row-major.
// BNN=0: B [N,K] row-major (NT).  BNN=1: B [K,N] row-major (NN, trans-ldmatrix).
// 128x128 CTA tile, K-step 32, 512 threads: 16 warps of 32x32 (warpM 0..3 x warpN 0..3),
// double-buffered cp.async.  OUTH=1 -> C half, OUTH=0 -> C float.
#define HS 40           // A (and NT-B) smem row stride in halfs
#define BP 136          // NN-B smem row pitch in halfs (128 + 8 pad -> 272 B)

template<int OUTH, int BNN>
__global__ __launch_bounds__(512, 1)
void gemm_h(const __half* __restrict__ A, long long lda, long long sA1, long long sA2,
            const __half* __restrict__ B, long long ldb, long long sB1, long long sB2,
            const float* __restrict__ bias,
            void* __restrict__ Cv, long long ldc, long long sC1, long long sC2,
            int K, float alpha, int bdiv)
{
    __shared__ __half As[2][128 * HS];
    __shared__ __half Bs[2][BNN ? (32 * BP) : (128 * HS)];

    const int bz = blockIdx.z;
    const int n_b = bz / bdiv, h_b = bz % bdiv;
    A += n_b * sA1 + h_b * sA2;
    B += n_b * sB1 + h_b * sB2;
    const long long coff = (long long)n_b * sC1 + (long long)h_b * sC2;
    __half* Ch = (__half*)Cv + coff;
    float*  Cf = (float*)Cv + coff;

    const int rowBase = blockIdx.y * 128;
    const int colBase = blockIdx.x * 128;
    const int tid  = threadIdx.x;
    const int wid  = tid >> 5;
    const int lane = tid & 31;
    const int warpM = wid >> 2;      // 0..3  (32 rows each)
    const int warpN = wid & 3;       // 0..3  (32 cols each)
    const int gid = lane >> 2;       // 0..7
    const int tig = lane & 3;        // 0..3

    // ---- A copy mapping: 512 threads, one cp16 each (128 rows x 32 k) ----
    const int crow = tid >> 2;                   // 0..127
    const int cslot = (tid & 3) * 8;             // halfs
    const __half* aSrc = A + (long long)(rowBase + crow) * lda + cslot;
    const unsigned aD0 = smem_u32(&As[0][crow * HS + cslot]);
    const unsigned aD1 = smem_u32(&As[1][crow * HS + cslot]);

    // ---- B copy mapping ----
    const __half* bSrc;
    unsigned bD0, bD1;
    if (BNN) {
        const int brow = tid >> 4;               // k-row 0..31
        const int bc   = (tid & 15) * 8;         // halfs 0..120
        bSrc = B + (long long)brow * ldb + colBase + bc;
        bD0 = smem_u32(&Bs[0][brow * BP + bc]);
        bD1 = smem_u32(&Bs[1][brow * BP + bc]);
    } else {
        bSrc = B + (long long)(colBase + crow) * ldb + cslot;
        bD0 = smem_u32(&Bs[0][crow * HS + cslot]);
        bD1 = smem_u32(&Bs[1][crow * HS + cslot]);
    }

    // ---- ldmatrix lane addresses ----
    // A x4 (per mt of 16 rows): lanes 0-15 -> rows 0-15 @k0; lanes 16-31 -> rows 0-15 @k8
    const int aRow = lane & 15;
    const int aK   = (lane >> 4) << 3;
    const unsigned aL0 = smem_u32(&As[0][(warpM * 32 + aRow) * HS + aK]);
    const unsigned aL1 = smem_u32(&As[1][(warpM * 32 + aRow) * HS + aK]);
    // B x4 batches two n-frags (p = nt pair index 0..1 covers nt=2p, 2p+1):
    unsigned bL0, bL1;
    if (BNN) {
        // trans: matrix m (lane group) -> (kRow = ks + (lane&7) + ((lane>>3)&1)*8,
        //                                  col  = warpN*32 + p*16 + (lane>>4)*8)
        const int kR = (lane & 7) + (((lane >> 3) & 1) << 3);
        const int nC = warpN * 32 + ((lane >> 4) << 3);
        bL0 = smem_u32(&Bs[0][kR * BP + nC]);
        bL1 = smem_u32(&Bs[1][kR * BP + nC]);
    } else {
        // non-trans: matrix m -> (n-row = warpN*32 + p*16 + (lane>>4)*8 + (lane&7),
        //                         k = ks + ((lane>>3)&1)*8)
        const int nR = warpN * 32 + ((lane >> 4) << 3) + (lane & 7);
        const int bK = ((lane >> 3) & 1) << 3;
        bL0 = smem_u32(&Bs[0][nR * HS + bK]);
        bL1 = smem_u32(&Bs[1][nR * HS + bK]);
    }

    float acc[2][4][4];
#pragma unroll
    for (int i = 0; i < 2; i++)
#pragma unroll
        for (int j = 0; j < 4; j++)
#pragma unroll
            for (int r = 0; r < 4; r++) acc[i][j][r] = 0.0f;

    const int KT = K >> 5;

    auto issue = [&](int kt) {
        const int k0 = kt << 5;
        const unsigned ad = (kt & 1) ? aD1 : aD0;
        const unsigned bd = (kt & 1) ? bD1 : bD0;
        cp16(ad, aSrc + k0);
        if (BNN) cp16(bd, bSrc + (long long)k0 * ldb);
        else     cp16(bd, bSrc + k0);
        asm volatile("cp.async.commit_group;" ::: "memory");
    };

    issue(0);

    for (int kt = 0; kt < KT; kt++) {
        if (kt + 1 < KT) {
            issue(kt + 1);
            asm volatile("cp.async.wait_group 1;" ::: "memory");
        } else {
            asm volatile("cp.async.wait_group 0;" ::: "memory");
        }
        __syncthreads();

        const unsigned aL = (kt & 1) ? aL1 : aL0;
        const unsigned bL = (kt & 1) ? bL1 : bL0;

#pragma unroll
        for (int ks = 0; ks < 32; ks += 16) {
            unsigned afr[2][4];
#pragma unroll
            for (int mt = 0; mt < 2; mt++)
                ldm_x4(afr[mt], aL + (mt * 16 * HS + ks) * 2);
            unsigned bfr[4][2];
#pragma unroll
            for (int p = 0; p < 2; p++) {
                unsigned r4[4];
                if (BNN) ldm_x4t(r4, bL + (ks * BP + p * 16) * 2);
                else     ldm_x4 (r4, bL + (p * 16 * HS + ks) * 2);
                bfr[2 * p][0] = r4[0]; bfr[2 * p][1] = r4[1];
                bfr[2 * p + 1][0] = r4[2]; bfr[2 * p + 1][1] = r4[3];
            }
#pragma unroll
            for (int mt = 0; mt < 2; mt++)
#pragma unroll
                for (int nt = 0; nt < 4; nt++)
                    mma_f16(acc[mt][nt], afr[mt], bfr[nt]);
        }
        __syncthreads();
    }

    // epilogue: warp tile 32x32 at (warpM*32, warpN*32)
#pragma unroll
    for (int mt = 0; mt < 2; mt++) {
        const int r0 = rowBase + warpM * 32 + mt * 16 + gid;
#pragma unroll
        for (int nt = 0; nt < 4; nt++) {
            const int c0 = colBase + warpN * 32 + nt * 8 + tig * 2;
            float b0 = 0.0f, b1 = 0.0f;
            if (bias) { b0 = bias[c0]; b1 = bias[c0 + 1]; }
            const float v00 = acc[mt][nt][0] * alpha + b0;
            const float v01 = acc[mt][nt][1] * alpha + b1;
            const float v10 = acc[mt][nt][2] * alpha + b0;
            const float v11 = acc[mt][nt][3] * alpha + b1;
            if (OUTH) {
                *(__half2*)(Ch + (long long)r0 * ldc + c0)       = __floats2half2_rn(v00, v01);
                *(__half2*)(Ch + (long long)(r0 + 8) * ldc + c0) = __floats2half2_rn(v10, v11);
            } else {
                *(float2*)(Cf + (long long)r0 * ldc + c0)       = make_float2(v00, v01);
                *(float2*)(Cf + (long long)(r0 + 8) * ldc + c0) = make_float2(v10, v11);
            }
        }
    }
}

// ---------------- fused prep: fp32 -> fp16 for 5 segments ----------------
__global__ __launch_bounds__(256)
void prep_all(const float4* s0, __half2* d0, int n0,
              const float4* s1, __half2* d1, int n1,
              const float4* s2, __half2* d2, int n2,
              const float4* s3, __half2* d3, int n3,
              const float4* s4, __half2* d4, int n4tot)
{
    const int total = n0 + n1 + n2 + n3 + n4tot;
    for (int i = blockIdx.x * blockDim.x + threadIdx.x; i < total;
         i += gridDim.x * blockDim.x) {
        const float4* s; __half2* d; int j = i;
        if (j < n0)                { s = s0; d = d0; }
        else if ((j -= n0) < n1)   { s = s1; d = d1; }
        else if ((j -= n1) < n2)   { s = s2; d = d2; }
        else if ((j -= n2) < n3)   { s = s3; d = d3; }
        else { j -= n3;              s = s4; d = d4; }
        const float4 v = s[j];
        d[2 * j]     = __floats2half2_rn(v.x, v.y);
        d[2 * j + 1] = __floats2half2_rn(v.z, v.w);
    }
}

// ---------------- warp-per-row softmax, rows of 512 halfs, in place ----------------
__global__ __launch_bounds__(256)
void softmax_warp(__half* __restrict__ P)
{
    const int row  = blockIdx.x * 8 + (threadIdx.x >> 5);
    const int lane = threadIdx.x & 31;
    uint4* p = (uint4*)(P + (long long)row * 512);   // 64 uint4 per row
    uint4 u0 = p[lane * 2];
    uint4 u1 = p[lane * 2 + 1];

    __half2* h0 = (__half2*)&u0;
    __half2* h1 = (__half2*)&u1;
    float v[16];
#pragma unroll
    for (int i = 0; i < 4; i++) {
        const float2 a = __half22float2(h0[i]);
        const float2 b = __half22float2(h1[i]);
        v[2 * i] = a.x; v[2 * i + 1] = a.y;
        v[8 + 2 * i] = b.x; v[8 + 2 * i + 1] = b.y;
    }
    float m = v[0];
#pragma unroll
    for (int i = 1; i < 16; i++) m = fmaxf(m, v[i]);
#pragma unroll
    for (int o = 16; o; o >>= 1) m = fmaxf(m, __shfl_xor_sync(0xFFFFFFFFu, m, o));
    float s = 0.0f;
#pragma unroll
    for (int i = 0; i < 16; i++) { v[i] = __expf(v[i] - m); s += v[i]; }
#pragma unroll
    for (int o = 16; o; o >>= 1) s += __shfl_xor_sync(0xFFFFFFFFu, s, o);
    const float inv = 1.0f / s;
#pragma unroll
    for (int i = 0; i < 4; i++) {
        h0[i] = __floats2half2_rn(v[2 * i] * inv, v[2 * i + 1] * inv);
        h1[i] = __floats2half2_rn(v[8 + 2 * i] * inv, v[8 + 2 * i + 1] * inv);
    }
    p[lane * 2]     = u0;
    p[lane * 2 + 1] = u1;
}

__global__ __launch_bounds__(256)
void pred_kernel(const float* __restrict__ xrec, float* __restrict__ xpred)
{
    const int idx = blockIdx.x * blockDim.x + threadIdx.x;
    const int c4 = idx & 15;
    const int t  = (idx >> 4) % 192;
    const int b  = idx / (16 * 192);
    const int s  = t % 48;
    const float4 v = *(const float4*)(xrec + (long long)b * 24576 + 7 * 3072 + s * 64 + c4 * 4);
    ((float4*)xpred)[idx] = v;
}

// ---------------- launch ----------------
extern "C" void kernel_launch(void* const* d_in, const int* in_sizes, int n_in,
                              void* d_out, int out_size)
{
    const float* x        = (const float*)d_in[0];
    const float* enc_W    = (const float*)d_in[1];
    const float* enc_b    = (const float*)d_in[2];
    const float* dec_W    = (const float*)d_in[3];
    const float* dec_b    = (const float*)d_in[4];
    const float* in_projW = (const float*)d_in[5];
    const float* in_projb = (const float*)d_in[6];
    const float* out_W    = (const float*)d_in[7];
    const float* out_b    = (const float*)d_in[8];
    float* out = (float*)d_out;

    __half *xh, *zh, *qkvh, *ph, *aoh, *zrech, *encWh, *inprojh, *outh, *decWh;
    cudaGetSymbolAddress((void**)&xh,      g_xh);
    cudaGetSymbolAddress((void**)&zh,      g_zh);
    cudaGetSymbolAddress((void**)&qkvh,    g_qkvh);
    cudaGetSymbolAddress((void**)&ph,      g_ph);
    cudaGetSymbolAddress((void**)&aoh,     g_aoh);
    cudaGetSymbolAddress((void**)&zrech,   g_zrech);
    cudaGetSymbolAddress((void**)&encWh,   g_encWh);
    cudaGetSymbolAddress((void**)&inprojh, g_inprojh);
    cudaGetSymbolAddress((void**)&outh,    g_outh);
    cudaGetSymbolAddress((void**)&decWh,   g_decWh);

    const float att_scale = 1.0f / sqrtf((float)HD);

    // 0) one fused convert pass
    prep_all<<<2048, 256>>>(
        (const float4*)x,        (__half2*)xh,      LROWS * DIN / 4,
        (const float4*)enc_W,    (__half2*)encWh,   DIN * EE / 4,
        (const float4*)in_projW, (__half2*)inprojh, 3 * EE * EE / 4,
        (const float4*)out_W,    (__half2*)outh,    EE * EE / 4,
        (const float4*)dec_W,    (__half2*)decWh,   EE * DIN / 4);

    // 1) z = x @ enc_W + enc_b              (NN, 4096x1024x3072) -> fp16
    gemm_h<1, 1><<<dim3(EE / 128, LROWS / 128, 1), 512>>>(
        xh, DIN, 0, 0, encWh, EE, 0, 0, enc_b,
        zh, EE, 0, 0, DIN, 1.0f, 1);

    // 2) qkv = z @ in_proj_W^T + b          (NT, 4096x3072x1024) -> fp16
    gemm_h<1, 0><<<dim3(3 * EE / 128, LROWS / 128, 1), 512>>>(
        zh, EE, 0, 0, inprojh, EE, 0, 0, in_projb,
        qkvh, 3 * EE, 0, 0, EE, 1.0f, 1);

    // 3) scores = alpha * Q @ K^T           (NT batched, 64 x 512x512x128) -> fp16
    gemm_h<1, 0><<<dim3(SEQ / 128, SEQ / 128, NH), 512>>>(
        qkvh,      LDQKV, 3 * EE, HD,
        qkvh + EE, LDQKV, 3 * EE, HD,
        nullptr,
        ph, SEQ, (long long)HH * SEQ * SEQ, (long long)SEQ * SEQ,
        HD, att_scale, HH);

    // 4) softmax in place (warp per row)
    softmax_warp<<<NH * SEQ / 8, 256>>>(ph);

    // 5) attn_o = P @ V into (L,N,E)        (NN batched, V in place from qkv)
    gemm_h<1, 1><<<dim3(HD / 128, SEQ / 128, NH), 512>>>(
        ph, SEQ, (long long)HH * SEQ * SEQ, (long long)SEQ * SEQ,
        qkvh + 2 * EE, LDQKV, 3 * EE, HD,
        nullptr,
        aoh, (long long)FREQ * EE, EE, HD,
        SEQ, 1.0f, HH);

    // 6) z_rec = attn_o @ out_W^T + b       (NT, 4096x1024x1024) -> fp16
    gemm_h<1, 0><<<dim3(EE / 128, LROWS / 128, 1), 512>>>(
        aoh, EE, 0, 0, outh, EE, 0, 0, out_b,
        zrech, EE, 0, 0, EE, 1.0f, 1);

    // 7) x_rec = z_rec @ dec_W + b -> d_out (NN, 4096x3072x1024) -> fp32
    gemm_h<0, 1><<<dim3(DIN / 128, LROWS / 128, 1), 512>>>(
        zrech, EE, 0, 0, decWh, DIN, 0, 0, dec_b,
        out, DIN, 0, 0, EE, 1.0f, 1);

    // 8) x_pred = tile of last chunk of x_rec
    pred_kernel<<<(BB * 192 * 64 / 4) / 256, 256>>>(out, out + (long long)BB * 384 * 64);
}

// round 12
// speedup vs baseline: 1.1388x; 1.1388x over previous
#include <cuda_runtime.h>
#include <cuda_fp16.h>
#include <math.h>

#define BB   512
#define FREQ 8
#define EE   1024
#define HH   8
#define HD   128
#define DIN  3072
#define LROWS 4096
#define SEQ  512
#define NH   64
#define LDQKV (3 * EE * FREQ)   // 24576 halfs between consecutive l (fixed n)

// fp16 tensors
__device__ __half g_xh[LROWS * DIN];
__device__ __half g_zh[LROWS * EE];
__device__ __half g_qkvh[LROWS * 3 * EE];
__device__ __half g_ph[NH * SEQ * SEQ];    // scores then P (in-place softmax)
__device__ __half g_aoh[LROWS * EE];
__device__ __half g_zrech[LROWS * EE];
__device__ __half g_encWh[DIN * EE];       // enc_W [3072][1024] (NN operand)
__device__ __half g_inprojh[3 * EE * EE];  // [3072][1024] (NT operand)
__device__ __half g_outh[EE * EE];         // [1024][1024] (NT operand)
__device__ __half g_decWh[EE * DIN];       // dec_W [1024][3072] (NN operand)

// ---------------- helpers ----------------
__device__ __forceinline__ unsigned smem_u32(const void* p) {
    unsigned a;
    asm("{ .reg .u64 t; cvta.to.shared.u64 t, %1; cvt.u32.u64 %0, t; }"
        : "=r"(a) : "l"(p));
    return a;
}
__device__ __forceinline__ void cp16(unsigned dst, const void* src) {
    asm volatile("cp.async.cg.shared.global [%0], [%1], 16;" :: "r"(dst), "l"(src));
}
__device__ __forceinline__ void mma_f16(float c[4], const unsigned a[4], const unsigned b[2]) {
    asm volatile(
        "mma.sync.aligned.m16n8k16.row.col.f32.f16.f16.f32 "
        "{%0,%1,%2,%3}, {%4,%5,%6,%7}, {%8,%9}, {%0,%1,%2,%3};\n"
        : "+f"(c[0]), "+f"(c[1]), "+f"(c[2]), "+f"(c[3])
        : "r"(a[0]), "r"(a[1]), "r"(a[2]), "r"(a[3]), "r"(b[0]), "r"(b[1]));
}
__device__ __forceinline__ void ldm_x4(unsigned* r, unsigned addr) {
    asm volatile("ldmatrix.sync.aligned.m8n8.x4.shared.b16 {%0,%1,%2,%3}, [%4];"
        : "=r"(r[0]), "=r"(r[1]), "=r"(r[2]), "=r"(r[3]) : "r"(addr));
}
__device__ __forceinline__ void ldm_x4t(unsigned* r, unsigned addr) {
    asm volatile("ldmatrix.sync.aligned.m8n8.x4.trans.shared.b16 {%0,%1,%2,%3}, [%4];"
        : "=r"(r[0]), "=r"(r[1]), "=r"(r[2]), "=r"(r[3]) : "r"(addr));
}

// ---------------- fp16 GEMM ----------------
// C = alpha * A @ op(B) + bias.  A:[M,K] half row-major.
// BNN=0: B [N,K] row-major (NT).  BNN=1: B [K,N] row-major (NN, trans-ldmatrix).
// 128x128 CTA tile, K-step 64, 512 threads: 16 warps of 32x32.
// Double-buffered cp.async, ONE __syncthreads per k-iter.
// OUTH=1 -> C half, OUTH=0 -> C float.
#define HS2 72          // A (and NT-B) smem row stride in halfs (64 k + 8 pad)
#define BP 136          // NN-B smem row pitch in halfs (128 + 8 pad -> 272 B)
#define ABUF (128 * HS2)                 // halfs per A stage
#define BBUF_NT (128 * HS2)
#define BBUF_NN (64 * BP)

template<int OUTH, int BNN>
__global__ __launch_bounds__(512, 1)
void gemm_h(const __half* __restrict__ A, long long lda, long long sA1, long long sA2,
            const __half* __restrict__ B, long long ldb, long long sB1, long long sB2,
            const float* __restrict__ bias,
            void* __restrict__ Cv, long long ldc, long long sC1, long long sC2,
            int K, float alpha, int bdiv)
{
    extern __shared__ __half sm[];
    constexpr int BBUF = BNN ? BBUF_NN : BBUF_NT;
    __half* As = sm;                  // [2][ABUF]
    __half* Bsm = sm + 2 * ABUF;      // [2][BBUF]

    const int bz = blockIdx.z;
    const int n_b = bz / bdiv, h_b = bz % bdiv;
    A += n_b * sA1 + h_b * sA2;
    B += n_b * sB1 + h_b * sB2;
    const long long coff = (long long)n_b * sC1 + (long long)h_b * sC2;
    __half* Ch = (__half*)Cv + coff;
    float*  Cf = (float*)Cv + coff;

    const int rowBase = blockIdx.y * 128;
    const int colBase = blockIdx.x * 128;
    const int tid  = threadIdx.x;
    const int wid  = tid >> 5;
    const int lane = tid & 31;
    const int warpM = wid >> 2;      // 0..3  (32 rows each)
    const int warpN = wid & 3;       // 0..3  (32 cols each)
    const int gid = lane >> 2;       // 0..7
    const int tig = lane & 3;        // 0..3

    // ---- A copy: 128 rows x 64 k per stage, 2 cp16/thread ----
    const int crow = tid >> 2;                   // 0..127
    const int c16  = (tid & 3) * 16;             // halfs 0,16,32,48
    const __half* aSrc = A + (long long)(rowBase + crow) * lda + c16;
    const unsigned aD0 = smem_u32(&As[crow * HS2 + c16]);
    const unsigned aD1 = aD0 + ABUF * 2;         // bytes

    // ---- B copy ----
    const __half* bSrc;
    unsigned bD0, bD1, bDrow2 = 0;               // NN second-row dst offset (bytes)
    long long bSrc2 = 0;
    if (BNN) {
        const int brow = tid >> 4;               // k-row 0..31 (and +32)
        const int bc   = (tid & 15) * 8;         // halfs 0..120
        bSrc = B + (long long)brow * ldb + colBase + bc;
        bSrc2 = 32LL * ldb;
        bD0 = smem_u32(&Bsm[brow * BP + bc]);
        bDrow2 = 32u * BP * 2u;
        bD1 = bD0 + BBUF * 2;
    } else {
        bSrc = B + (long long)(colBase + crow) * ldb + c16;
        bD0 = smem_u32(&Bsm[crow * HS2 + c16]);
        bD1 = bD0 + BBUF * 2;
    }

    // ---- ldmatrix lane addresses ----
    const int aRow = lane & 15;
    const int aK   = (lane >> 4) << 3;
    const unsigned aL0 = smem_u32(&As[(warpM * 32 + aRow) * HS2 + aK]);
    const unsigned aL1 = aL0 + ABUF * 2;
    unsigned bL0, bL1;
    if (BNN) {
        const int kR = (lane & 7) + (((lane >> 3) & 1) << 3);
        const int nC = warpN * 32 + ((lane >> 4) << 3);
        bL0 = smem_u32(&Bsm[kR * BP + nC]);
        bL1 = bL0 + BBUF * 2;
    } else {
        const int nR = warpN * 32 + ((lane >> 4) << 3) + (lane & 7);
        const int bK = ((lane >> 3) & 1) << 3;
        bL0 = smem_u32(&Bsm[nR * HS2 + bK]);
        bL1 = bL0 + BBUF * 2;
    }

    float acc[2][4][4];
#pragma unroll
    for (int i = 0; i < 2; i++)
#pragma unroll
        for (int j = 0; j < 4; j++)
#pragma unroll
            for (int r = 0; r < 4; r++) acc[i][j][r] = 0.0f;

    const int KT = K >> 6;

    auto issue = [&](int kt) {
        const int k0 = kt << 6;
        const unsigned ad = (kt & 1) ? aD1 : aD0;
        const unsigned bd = (kt & 1) ? bD1 : bD0;
        cp16(ad,      aSrc + k0);
        cp16(ad + 16, aSrc + k0 + 8);
        if (BNN) {
            const __half* bs = bSrc + (long long)k0 * ldb;
            cp16(bd,          bs);
            cp16(bd + bDrow2, bs + bSrc2);
        } else {
            cp16(bd,      bSrc + k0);
            cp16(bd + 16, bSrc + k0 + 8);
        }
        asm volatile("cp.async.commit_group;" ::: "memory");
    };

    issue(0);

    for (int kt = 0; kt < KT; kt++) {
        asm volatile("cp.async.wait_group 0;" ::: "memory");
        __syncthreads();                 // single barrier per k-iter
        if (kt + 1 < KT) issue(kt + 1);  // overlaps with compute below

        const unsigned aL = (kt & 1) ? aL1 : aL0;
        const unsigned bL = (kt & 1) ? bL1 : bL0;

#pragma unroll
        for (int ks = 0; ks < 64; ks += 16) {
            unsigned afr[2][4];
#pragma unroll
            for (int mt = 0; mt < 2; mt++)
                ldm_x4(afr[mt], aL + (mt * 16 * HS2 + ks) * 2);
            unsigned bfr[4][2];
#pragma unroll
            for (int p = 0; p < 2; p++) {
                unsigned r4[4];
                if (BNN) ldm_x4t(r4, bL + (ks * BP + p * 16) * 2);
                else     ldm_x4 (r4, bL + (p * 16 * HS2 + ks) * 2);
                bfr[2 * p][0] = r4[0]; bfr[2 * p][1] = r4[1];
                bfr[2 * p + 1][0] = r4[2]; bfr[2 * p + 1][1] = r4[3];
            }
#pragma unroll
            for (int mt = 0; mt < 2; mt++)
#pragma unroll
                for (int nt = 0; nt < 4; nt++)
                    mma_f16(acc[mt][nt], afr[mt], bfr[nt]);
        }
    }

    // epilogue: warp tile 32x32 at (warpM*32, warpN*32)
#pragma unroll
    for (int mt = 0; mt < 2; mt++) {
        const int r0 = rowBase + warpM * 32 + mt * 16 + gid;
#pragma unroll
        for (int nt = 0; nt < 4; nt++) {
            const int c0 = colBase + warpN * 32 + nt * 8 + tig * 2;
            float b0 = 0.0f, b1 = 0.0f;
            if (bias) { b0 = bias[c0]; b1 = bias[c0 + 1]; }
            const float v00 = acc[mt][nt][0] * alpha + b0;
            const float v01 = acc[mt][nt][1] * alpha + b1;
            const float v10 = acc[mt][nt][2] * alpha + b0;
            const float v11 = acc[mt][nt][3] * alpha + b1;
            if (OUTH) {
                *(__half2*)(Ch + (long long)r0 * ldc + c0)       = __floats2half2_rn(v00, v01);
                *(__half2*)(Ch + (long long)(r0 + 8) * ldc + c0) = __floats2half2_rn(v10, v11);
            } else {
                *(float2*)(Cf + (long long)r0 * ldc + c0)       = make_float2(v00, v01);
                *(float2*)(Cf + (long long)(r0 + 8) * ldc + c0) = make_float2(v10, v11);
            }
        }
    }
}

// ---------------- fused prep: fp32 -> fp16 for 5 segments ----------------
__global__ __launch_bounds__(256)
void prep_all(const float4* s0, __half2* d0, int n0,
              const float4* s1, __half2* d1, int n1,
              const float4* s2, __half2* d2, int n2,
              const float4* s3, __half2* d3, int n3,
              const float4* s4, __half2* d4, int n4tot)
{
    const int total = n0 + n1 + n2 + n3 + n4tot;
    for (int i = blockIdx.x * blockDim.x + threadIdx.x; i < total;
         i += gridDim.x * blockDim.x) {
        const float4* s; __half2* d; int j = i;
        if (j < n0)                { s = s0; d = d0; }
        else if ((j -= n0) < n1)   { s = s1; d = d1; }
        else if ((j -= n1) < n2)   { s = s2; d = d2; }
        else if ((j -= n2) < n3)   { s = s3; d = d3; }
        else { j -= n3;              s = s4; d = d4; }
        const float4 v = s[j];
        d[2 * j]     = __floats2half2_rn(v.x, v.y);
        d[2 * j + 1] = __floats2half2_rn(v.z, v.w);
    }
}

// ---------------- warp-per-row softmax, rows of 512 halfs, in place ----------------
__global__ __launch_bounds__(256)
void softmax_warp(__half* __restrict__ P)
{
    const int row  = blockIdx.x * 8 + (threadIdx.x >> 5);
    const int lane = threadIdx.x & 31;
    uint4* p = (uint4*)(P + (long long)row * 512);   // 64 uint4 per row
    uint4 u0 = p[lane * 2];
    uint4 u1 = p[lane * 2 + 1];

    __half2* h0 = (__half2*)&u0;
    __half2* h1 = (__half2*)&u1;
    float v[16];
#pragma unroll
    for (int i = 0; i < 4; i++) {
        const float2 a = __half22float2(h0[i]);
        const float2 b = __half22float2(h1[i]);
        v[2 * i] = a.x; v[2 * i + 1] = a.y;
        v[8 + 2 * i] = b.x; v[8 + 2 * i + 1] = b.y;
    }
    float m = v[0];
#pragma unroll
    for (int i = 1; i < 16; i++) m = fmaxf(m, v[i]);
#pragma unroll
    for (int o = 16; o; o >>= 1) m = fmaxf(m, __shfl_xor_sync(0xFFFFFFFFu, m, o));
    float s = 0.0f;
#pragma unroll
    for (int i = 0; i < 16; i++) { v[i] = __expf(v[i] - m); s += v[i]; }
#pragma unroll
    for (int o = 16; o; o >>= 1) s += __shfl_xor_sync(0xFFFFFFFFu, s, o);
    const float inv = 1.0f / s;
#pragma unroll
    for (int i = 0; i < 4; i++) {
        h0[i] = __floats2half2_rn(v[2 * i] * inv, v[2 * i + 1] * inv);
        h1[i] = __floats2half2_rn(v[8 + 2 * i] * inv, v[8 + 2 * i + 1] * inv);
    }
    p[lane * 2]     = u0;
    p[lane * 2 + 1] = u1;
}

__global__ __launch_bounds__(256)
void pred_kernel(const float* __restrict__ xrec, float* __restrict__ xpred)
{
    const int idx = blockIdx.x * blockDim.x + threadIdx.x;
    const int c4 = idx & 15;
    const int t  = (idx >> 4) % 192;
    const int b  = idx / (16 * 192);
    const int s  = t % 48;
    const float4 v = *(const float4*)(xrec + (long long)b * 24576 + 7 * 3072 + s * 64 + c4 * 4);
    ((float4*)xpred)[idx] = v;
}

// ---------------- launch ----------------
extern "C" void kernel_launch(void* const* d_in, const int* in_sizes, int n_in,
                              void* d_out, int out_size)
{
    const float* x        = (const float*)d_in[0];
    const float* enc_W    = (const float*)d_in[1];
    const float* enc_b    = (const float*)d_in[2];
    const float* dec_W    = (const float*)d_in[3];
    const float* dec_b    = (const float*)d_in[4];
    const float* in_projW = (const float*)d_in[5];
    const float* in_projb = (const float*)d_in[6];
    const float* out_W    = (const float*)d_in[7];
    const float* out_b    = (const float*)d_in[8];
    float* out = (float*)d_out;

    __half *xh, *zh, *qkvh, *ph, *aoh, *zrech, *encWh, *inprojh, *outh, *decWh;
    cudaGetSymbolAddress((void**)&xh,      g_xh);
    cudaGetSymbolAddress((void**)&zh,      g_zh);
    cudaGetSymbolAddress((void**)&qkvh,    g_qkvh);
    cudaGetSymbolAddress((void**)&ph,      g_ph);
    cudaGetSymbolAddress((void**)&aoh,     g_aoh);
    cudaGetSymbolAddress((void**)&zrech,   g_zrech);
    cudaGetSymbolAddress((void**)&encWh,   g_encWh);
    cudaGetSymbolAddress((void**)&inprojh, g_inprojh);
    cudaGetSymbolAddress((void**)&outh,    g_outh);
    cudaGetSymbolAddress((void**)&decWh,   g_decWh);

    const int SM_NT = 2 * (ABUF + BBUF_NT) * 2;   // 73728 B
    const int SM_NN = 2 * (ABUF + BBUF_NN) * 2;   // 71168 B
    cudaFuncSetAttribute(gemm_h<1, 0>, cudaFuncAttributeMaxDynamicSharedMemorySize, SM_NT);
    cudaFuncSetAttribute(gemm_h<1, 1>, cudaFuncAttributeMaxDynamicSharedMemorySize, SM_NN);
    cudaFuncSetAttribute(gemm_h<0, 1>, cudaFuncAttributeMaxDynamicSharedMemorySize, SM_NN);

    const float att_scale = 1.0f / sqrtf((float)HD);

    // 0) one fused convert pass
    prep_all<<<2048, 256>>>(
        (const float4*)x,        (__half2*)xh,      LROWS * DIN / 4,
        (const float4*)enc_W,    (__half2*)encWh,   DIN * EE / 4,
        (const float4*)in_projW, (__half2*)inprojh, 3 * EE * EE / 4,
        (const float4*)out_W,    (__half2*)outh,    EE * EE / 4,
        (const float4*)dec_W,    (__half2*)decWh,   EE * DIN / 4);

    // 1) z = x @ enc_W + enc_b              (NN, 4096x1024x3072) -> fp16
    gemm_h<1, 1><<<dim3(EE / 128, LROWS / 128, 1), 512, SM_NN>>>(
        xh, DIN, 0, 0, encWh, EE, 0, 0, enc_b,
        zh, EE, 0, 0, DIN, 1.0f, 1);

    // 2) qkv = z @ in_proj_W^T + b          (NT, 4096x3072x1024) -> fp16
    gemm_h<1, 0><<<dim3(3 * EE / 128, LROWS / 128, 1), 512, SM_NT>>>(
        zh, EE, 0, 0, inprojh, EE, 0, 0, in_projb,
        qkvh, 3 * EE, 0, 0, EE, 1.0f, 1);

    // 3) scores = alpha * Q @ K^T           (NT batched, 64 x 512x512x128) -> fp16
    gemm_h<1, 0><<<dim3(SEQ / 128, SEQ / 128, NH), 512, SM_NT>>>(
        qkvh,      LDQKV, 3 * EE, HD,
        qkvh + EE, LDQKV, 3 * EE, HD,
        nullptr,
        ph, SEQ, (long long)HH * SEQ * SEQ, (long long)SEQ * SEQ,
        HD, att_scale, HH);

    // 4) softmax in place (warp per row)
    softmax_warp<<<NH * SEQ / 8, 256>>>(ph);

    // 5) attn_o = P @ V into (L,N,E)        (NN batched, V in place from qkv)
    gemm_h<1, 1><<<dim3(HD / 128, SEQ / 128, NH), 512, SM_NN>>>(
        ph, SEQ, (long long)HH * SEQ * SEQ, (long long)SEQ * SEQ,
        qkvh + 2 * EE, LDQKV, 3 * EE, HD,
        nullptr,
        aoh, (long long)FREQ * EE, EE, HD,
        SEQ, 1.0f, HH);

    // 6) z_rec = attn_o @ out_W^T + b       (NT, 4096x1024x1024) -> fp16
    gemm_h<1, 0><<<dim3(EE / 128, LROWS / 128, 1), 512, SM_NT>>>(
        aoh, EE, 0, 0, outh, EE, 0, 0, out_b,
        zrech, EE, 0, 0, EE, 1.0f, 1);

    // 7) x_rec = z_rec @ dec_W + b -> d_out (NN, 4096x3072x1024) -> fp32
    gemm_h<0, 1><<<dim3(DIN / 128, LROWS / 128, 1), 512, SM_NN>>>(
        zrech, EE, 0, 0, decWh, DIN, 0, 0, dec_b,
        out, DIN, 0, 0, EE, 1.0f, 1);

    // 8) x_pred = tile of last chunk of x_rec
    pred_kernel<<<(BB * 192 * 64 / 4) / 256, 256>>>(out, out + (long long)BB * 384 * 64);
}